// round 2
// baseline (speedup 1.0000x reference)
#include <cuda_runtime.h>
#include <math.h>

// Problem constants
#define BB   4
#define CC   256
#define C4   64
#define HWN  4096

// Scratch (static device arrays; no allocation)
__device__ float g_q [BB * C4 * HWN];          // [b][c][hw]
__device__ float g_kl[BB * C4 * HWN];          // [b][c][hw]
__device__ float g_kf[BB * C4 * HWN];          // [b][c][hw]
__device__ float g_v [BB * HWN * C4];          // [b][hw][c]  (k-major for GEMM2)
__device__ float g_fused[BB * HWN * 128];      // [b][hw][cf] (cf: 0-63 = out_l, 64-127 = out_f)

// ---------------------------------------------------------------------------
// Kernel 1: projections.  Y = W[64,256] @ X[256,4096] + bias  (per batch, 4 proj)
// grid (32 hw-tiles, B, 4 proj), block 256. Tile 64 rows x 128 cols.
// proj 3 (v) is written transposed to [hw][c].
// ---------------------------------------------------------------------------
__global__ __launch_bounds__(256) void proj_kernel(
    const float* __restrict__ last, const float* __restrict__ cur, const float* __restrict__ fut,
    const float* __restrict__ Wqk, const float* __restrict__ bqk,
    const float* __restrict__ Wkl, const float* __restrict__ bkl,
    const float* __restrict__ Wkf, const float* __restrict__ bkf,
    const float* __restrict__ Wv,  const float* __restrict__ bv)
{
    __shared__ float Ws[32 * 64];    // Ws[k][r]
    __shared__ float Xs[32 * 128];   // Xs[k][col]

    const int tile = blockIdx.x;     // 0..31
    const int b    = blockIdx.y;
    const int p    = blockIdx.z;     // 0..3

    const float* X; const float* W; const float* bias;
    if      (p == 0) { X = cur;  W = Wqk; bias = bqk; }
    else if (p == 1) { X = last; W = Wkl; bias = bkl; }
    else if (p == 2) { X = fut;  W = Wkf; bias = bkf; }
    else             { X = cur;  W = Wv;  bias = bv;  }

    const float* Xb = X + (size_t)b * CC * HWN;
    const int col0 = tile * 128;
    const int t  = threadIdx.x;
    const int ty = t >> 5;           // 0..7  -> rows ty*8..+7
    const int tx = t & 31;           // 0..31 -> cols tx*4..+3

    float acc[8][4];
    #pragma unroll
    for (int i = 0; i < 8; ++i)
        #pragma unroll
        for (int j = 0; j < 4; ++j) acc[i][j] = 0.f;

    for (int kk = 0; kk < CC; kk += 32) {
        // Ws[k][r] = W[r][kk+k]  (transposed load; conflict-free STS: bank = r%32)
        #pragma unroll
        for (int pp = 0; pp < 2; ++pp) {
            int idx = t + pp * 256;          // 0..511
            int r   = idx & 63;
            int k4  = (idx >> 6) * 4;        // 0,4,...,28
            float4 w = *(const float4*)&W[r * 256 + kk + k4];
            Ws[(k4 + 0) * 64 + r] = w.x;
            Ws[(k4 + 1) * 64 + r] = w.y;
            Ws[(k4 + 2) * 64 + r] = w.z;
            Ws[(k4 + 3) * 64 + r] = w.w;
        }
        // Xs[k][col] = X[kk+k][col0+col]  (coalesced float4)
        #pragma unroll
        for (int pp = 0; pp < 4; ++pp) {
            int idx  = t + pp * 256;         // 0..1023 float4 slots
            int k    = idx >> 5;             // 0..31
            int c4   = (idx & 31) * 4;       // 0..124
            *(float4*)&Xs[k * 128 + c4] =
                *(const float4*)&Xb[(size_t)(kk + k) * HWN + col0 + c4];
        }
        __syncthreads();
        #pragma unroll 8
        for (int k = 0; k < 32; ++k) {
            float4 x  = *(const float4*)&Xs[k * 128 + tx * 4];
            float4 w0 = *(const float4*)&Ws[k * 64 + ty * 8];
            float4 w1 = *(const float4*)&Ws[k * 64 + ty * 8 + 4];
            float wr[8] = {w0.x, w0.y, w0.z, w0.w, w1.x, w1.y, w1.z, w1.w};
            float xc[4] = {x.x, x.y, x.z, x.w};
            #pragma unroll
            for (int i = 0; i < 8; ++i)
                #pragma unroll
                for (int j = 0; j < 4; ++j)
                    acc[i][j] += wr[i] * xc[j];
        }
        __syncthreads();
    }

    if (p < 3) {
        float* out = (p == 0 ? g_q : (p == 1 ? g_kl : g_kf)) + (size_t)b * C4 * HWN;
        #pragma unroll
        for (int i = 0; i < 8; ++i) {
            int r = ty * 8 + i;
            float bb = bias[r];
            float4 v = make_float4(acc[i][0] + bb, acc[i][1] + bb,
                                   acc[i][2] + bb, acc[i][3] + bb);
            *(float4*)&out[(size_t)r * HWN + col0 + tx * 4] = v;
        }
    } else {
        // v transposed: g_v[b][hw][c]
        #pragma unroll
        for (int i = 0; i < 8; ++i) {
            int r = ty * 8 + i;
            float bb = bias[r];
            #pragma unroll
            for (int j = 0; j < 4; ++j)
                g_v[((size_t)b * HWN + col0 + tx * 4 + j) * C4 + r] = acc[i][j] + bb;
        }
    }
}

// ---------------------------------------------------------------------------
// Kernel 2: fused flash attention (both sides). grid (64 qtiles, B, 2 sides).
// Per CTA: 64 queries x full 4096 keys in 64-key tiles, online softmax.
// 256 threads: ty=t/16 -> q rows ty*4..+3 ; tx=t%16 -> (S: keys tx*4..+3,
// O: channels tx*4..+3). 16-lane row groups == half warps -> shfl reductions.
// ---------------------------------------------------------------------------
__global__ __launch_bounds__(256) void attn_kernel()
{
    __shared__ float Qs [64 * 64];   // Qs[c][q]
    __shared__ float KPs[64 * 64];   // K tile [c][k], reused as P tile [q][k]
    __shared__ float Vt [64 * 64];   // Vt[k][c]

    const int qt   = blockIdx.x;     // 0..63
    const int b    = blockIdx.y;
    const int side = blockIdx.z;

    const float* Qg = g_q + (size_t)b * C4 * HWN;
    const float* Kg = (side == 0 ? g_kl : g_kf) + (size_t)b * C4 * HWN;
    const float* Vg = g_v + (size_t)b * HWN * C4;

    const int q0 = qt * 64;
    const int t  = threadIdx.x;
    const int ty = t >> 4;           // 0..15
    const int tx = t & 15;           // 0..15

    #pragma unroll
    for (int pp = 0; pp < 4; ++pp) {
        int idx = t + pp * 256;      // float4 slots
        int c   = idx >> 4;
        int q4  = (idx & 15) * 4;
        *(float4*)&Qs[c * 64 + q4] = *(const float4*)&Qg[(size_t)c * HWN + q0 + q4];
    }

    float m_run[4], l_run[4], o[4][4];
    #pragma unroll
    for (int i = 0; i < 4; ++i) {
        m_run[i] = -INFINITY; l_run[i] = 0.f;
        #pragma unroll
        for (int j = 0; j < 4; ++j) o[i][j] = 0.f;
    }

    for (int k0 = 0; k0 < HWN; k0 += 64) {
        __syncthreads();   // protect KPs/Vt from previous iteration readers (covers Q load on iter 0)
        #pragma unroll
        for (int pp = 0; pp < 4; ++pp) {
            int idx = t + pp * 256;
            int c   = idx >> 4;
            int k4  = (idx & 15) * 4;
            *(float4*)&KPs[c * 64 + k4] = *(const float4*)&Kg[(size_t)c * HWN + k0 + k4];
        }
        #pragma unroll
        for (int pp = 0; pp < 4; ++pp) {
            int idx = t + pp * 256;
            int kk  = idx >> 4;
            int c4  = (idx & 15) * 4;
            *(float4*)&Vt[kk * 64 + c4] = *(const float4*)&Vg[(size_t)(k0 + kk) * C4 + c4];
        }
        __syncthreads();

        // GEMM1: S[q][k] = sum_c Q[c][q] * K[c][k]
        float s[4][4];
        #pragma unroll
        for (int i = 0; i < 4; ++i)
            #pragma unroll
            for (int j = 0; j < 4; ++j) s[i][j] = 0.f;

        #pragma unroll 8
        for (int c = 0; c < 64; ++c) {
            float4 qv = *(const float4*)&Qs [c * 64 + ty * 4];
            float4 kv = *(const float4*)&KPs[c * 64 + tx * 4];
            float qa[4] = {qv.x, qv.y, qv.z, qv.w};
            float ka[4] = {kv.x, kv.y, kv.z, kv.w};
            #pragma unroll
            for (int i = 0; i < 4; ++i)
                #pragma unroll
                for (int j = 0; j < 4; ++j)
                    s[i][j] += qa[i] * ka[j];
        }

        // online softmax per q-row (reduce across 16 lanes = half warp)
        float alpha[4];
        #pragma unroll
        for (int i = 0; i < 4; ++i) {
            float tm = fmaxf(fmaxf(s[i][0], s[i][1]), fmaxf(s[i][2], s[i][3]));
            #pragma unroll
            for (int off = 8; off > 0; off >>= 1)
                tm = fmaxf(tm, __shfl_xor_sync(0xffffffffu, tm, off));
            float nm = fmaxf(m_run[i], tm);
            alpha[i] = __expf(m_run[i] - nm);
            m_run[i] = nm;
            float rs = 0.f;
            #pragma unroll
            for (int j = 0; j < 4; ++j) { s[i][j] = __expf(s[i][j] - nm); rs += s[i][j]; }
            #pragma unroll
            for (int off = 8; off > 0; off >>= 1)
                rs += __shfl_xor_sync(0xffffffffu, rs, off);
            l_run[i] = l_run[i] * alpha[i] + rs;
            #pragma unroll
            for (int j = 0; j < 4; ++j) o[i][j] *= alpha[i];
        }

        __syncthreads();   // everyone done reading KPs as K
        #pragma unroll
        for (int i = 0; i < 4; ++i)
            *(float4*)&KPs[(ty * 4 + i) * 64 + tx * 4] =
                make_float4(s[i][0], s[i][1], s[i][2], s[i][3]);
        __syncthreads();

        // GEMM2: O[q][c] += sum_k P[q][k] * V[k][c]
        #pragma unroll 8
        for (int k = 0; k < 64; ++k) {
            float4 vv = *(const float4*)&Vt[k * 64 + tx * 4];
            float p0 = KPs[(ty * 4 + 0) * 64 + k];
            float p1 = KPs[(ty * 4 + 1) * 64 + k];
            float p2 = KPs[(ty * 4 + 2) * 64 + k];
            float p3 = KPs[(ty * 4 + 3) * 64 + k];
            float va[4] = {vv.x, vv.y, vv.z, vv.w};
            float pa[4] = {p0, p1, p2, p3};
            #pragma unroll
            for (int i = 0; i < 4; ++i)
                #pragma unroll
                for (int j = 0; j < 4; ++j)
                    o[i][j] += pa[i] * va[j];
        }
    }

    // epilogue: normalize, write g_fused[b][hw][cf]
    #pragma unroll
    for (int i = 0; i < 4; ++i) {
        float invl = 1.f / l_run[i];
        float4 r = make_float4(o[i][0] * invl, o[i][1] * invl,
                               o[i][2] * invl, o[i][3] * invl);
        *(float4*)&g_fused[((size_t)b * HWN + q0 + ty * 4 + i) * 128 + side * 64 + tx * 4] = r;
    }
}

// ---------------------------------------------------------------------------
// Kernel 3: fire conv + BN + residual + ReLU.
// fired = Wfire[256,128] @ fused[128,4096]; out = relu(cur + fired*inv + shift)
// grid (32 hw-tiles, 4 row-tiles, B), block 256. Tile 64 rows x 128 cols, K=128.
// ---------------------------------------------------------------------------
__global__ __launch_bounds__(256) void fire_kernel(
    const float* __restrict__ cur,
    const float* __restrict__ Wfire, const float* __restrict__ bfire,
    const float* __restrict__ gamma, const float* __restrict__ beta,
    const float* __restrict__ mean,  const float* __restrict__ var,
    float* __restrict__ out)
{
    __shared__ float Ws[32 * 64];     // Ws[k][r]
    __shared__ float Xs[32 * 132];    // Xs[k][col], pitch 132 (float4-readable)

    const int tile = blockIdx.x;      // 0..31
    const int rt   = blockIdx.y;      // 0..3
    const int b    = blockIdx.z;
    const int r0   = rt * 64;
    const int col0 = tile * 128;
    const int t  = threadIdx.x;
    const int ty = t >> 5;
    const int tx = t & 31;

    const float* Fb = g_fused + (size_t)b * HWN * 128;

    float acc[8][4];
    #pragma unroll
    for (int i = 0; i < 8; ++i)
        #pragma unroll
        for (int j = 0; j < 4; ++j) acc[i][j] = 0.f;

    for (int kk = 0; kk < 128; kk += 32) {
        #pragma unroll
        for (int pp = 0; pp < 2; ++pp) {
            int idx = t + pp * 256;
            int r   = idx & 63;
            int k4  = (idx >> 6) * 4;
            float4 w = *(const float4*)&Wfire[(r0 + r) * 128 + kk + k4];
            Ws[(k4 + 0) * 64 + r] = w.x;
            Ws[(k4 + 1) * 64 + r] = w.y;
            Ws[(k4 + 2) * 64 + r] = w.z;
            Ws[(k4 + 3) * 64 + r] = w.w;
        }
        // transpose-load fused[hw-major] into Xs[k][col]
        #pragma unroll
        for (int pp = 0; pp < 4; ++pp) {
            int idx = t + pp * 256;          // 0..1023
            int col = idx >> 3;              // 0..127
            int k4  = (idx & 7) * 4;         // 0..28
            float4 x = *(const float4*)&Fb[(size_t)(col0 + col) * 128 + kk + k4];
            Xs[(k4 + 0) * 132 + col] = x.x;
            Xs[(k4 + 1) * 132 + col] = x.y;
            Xs[(k4 + 2) * 132 + col] = x.z;
            Xs[(k4 + 3) * 132 + col] = x.w;
        }
        __syncthreads();
        #pragma unroll 8
        for (int k = 0; k < 32; ++k) {
            float4 x  = *(const float4*)&Xs[k * 132 + tx * 4];
            float4 w0 = *(const float4*)&Ws[k * 64 + ty * 8];
            float4 w1 = *(const float4*)&Ws[k * 64 + ty * 8 + 4];
            float wr[8] = {w0.x, w0.y, w0.z, w0.w, w1.x, w1.y, w1.z, w1.w};
            float xc[4] = {x.x, x.y, x.z, x.w};
            #pragma unroll
            for (int i = 0; i < 8; ++i)
                #pragma unroll
                for (int j = 0; j < 4; ++j)
                    acc[i][j] += wr[i] * xc[j];
        }
        __syncthreads();
    }

    const float* curb = cur + (size_t)b * CC * HWN;
    #pragma unroll
    for (int i = 0; i < 8; ++i) {
        int r = r0 + ty * 8 + i;
        float inv   = gamma[r] * rsqrtf(var[r] + 1e-5f);
        float shift = beta[r] - mean[r] * inv;
        float bb    = bfire[r];
        size_t base = (size_t)r * HWN + col0 + tx * 4;
        float4 c4 = *(const float4*)&curb[base];
        float4 rv;
        rv.x = fmaxf(c4.x + (acc[i][0] + bb) * inv + shift, 0.f);
        rv.y = fmaxf(c4.y + (acc[i][1] + bb) * inv + shift, 0.f);
        rv.z = fmaxf(c4.z + (acc[i][2] + bb) * inv + shift, 0.f);
        rv.w = fmaxf(c4.w + (acc[i][3] + bb) * inv + shift, 0.f);
        *(float4*)&out[(size_t)b * CC * HWN + base] = rv;
    }
}

// ---------------------------------------------------------------------------
extern "C" void kernel_launch(void* const* d_in, const int* in_sizes, int n_in,
                              void* d_out, int out_size)
{
    const float* last  = (const float*)d_in[0];
    const float* cur   = (const float*)d_in[1];
    const float* fut   = (const float*)d_in[2];
    const float* Wqk   = (const float*)d_in[3];
    const float* bqk   = (const float*)d_in[4];
    const float* Wkl   = (const float*)d_in[5];
    const float* bkl   = (const float*)d_in[6];
    const float* Wkf   = (const float*)d_in[7];
    const float* bkf   = (const float*)d_in[8];
    const float* Wv    = (const float*)d_in[9];
    const float* bv    = (const float*)d_in[10];
    const float* Wfire = (const float*)d_in[11];
    const float* bfire = (const float*)d_in[12];
    const float* gamma = (const float*)d_in[13];
    const float* beta  = (const float*)d_in[14];
    const float* mean  = (const float*)d_in[15];
    const float* var   = (const float*)d_in[16];

    proj_kernel<<<dim3(32, BB, 4), 256>>>(last, cur, fut,
                                          Wqk, bqk, Wkl, bkl, Wkf, bkf, Wv, bv);
    attn_kernel<<<dim3(64, BB, 2), 256>>>();
    fire_kernel<<<dim3(32, 4, BB), 256>>>(cur, Wfire, bfire,
                                          gamma, beta, mean, var, (float*)d_out);
}